// round 1
// baseline (speedup 1.0000x reference)
#include <cuda_runtime.h>

// MedianBlur 5x5, fp32, 12 images of 1024x1024, zero padding (same).
// Strategy: shared-memory tile; each thread computes 4 horizontally adjacent
// outputs. Sorted-column reuse + doubly-sorted-matrix candidate-band selection
// (median of 25 == median of the 13 band candidates == med7 reduction).

#define IMG_H 1024
#define IMG_W 1024
#define NIMG  12

#define TILE_W 128            // output cols per block (32 threads * 4 px)
#define TILE_H 8              // output rows per block
#define SMEM_W (TILE_W + 4)   // 132
#define SMEM_H (TILE_H + 4)   // 12

__device__ __forceinline__ void ce(float& a, float& b) {
    float t = fminf(a, b);
    b = fmaxf(a, b);
    a = t;
}

// 9-CE optimal sorting network for 5 elements (ascending).
__device__ __forceinline__ void sort5(float& v0, float& v1, float& v2, float& v3, float& v4) {
    ce(v0, v1); ce(v3, v4); ce(v2, v4); ce(v2, v3); ce(v0, v3);
    ce(v0, v2); ce(v1, v4); ce(v1, v3); ce(v1, v2);
}

// Merge sorted pair (a0<=a1) with sorted triple (b0<=b1<=b2) -> m0..m4 (6 CE).
__device__ __forceinline__ void merge23(float a0, float a1,
                                        float b0, float b1, float b2,
                                        float& m0, float& m1, float& m2,
                                        float& m3, float& m4) {
    // insert a0 into b
    float x0 = fminf(a0, b0); float y0 = fmaxf(a0, b0);
    float x1 = fminf(y0, b1); float y1 = fmaxf(y0, b1);
    float x2 = fminf(y1, b2); float x3 = fmaxf(y1, b2);
    // a1 >= a0 >= x0, so insert a1 into (x1,x2,x3)
    float w1 = fminf(a1, x1); float z1 = fmaxf(a1, x1);
    float w2 = fminf(z1, x2); float z2 = fmaxf(z1, x2);
    float w3 = fminf(z2, x3); float w4 = fmaxf(z2, x3);
    m0 = x0; m1 = w1; m2 = w2; m3 = w3; m4 = w4;
}

// Merge two sorted pairs -> m0..m3 (3 CE).
__device__ __forceinline__ void merge22(float a0, float a1, float b0, float b1,
                                        float& m0, float& m1, float& m2, float& m3) {
    m0 = fminf(a0, b0); float t = fmaxf(a0, b0);
    m3 = fmaxf(a1, b1); float u = fminf(a1, b1);
    m1 = fminf(t, u);   m2 = fmaxf(t, u);
}

// Batcher odd-even merge of two sorted triples -> z0..z5 (6 CE).
__device__ __forceinline__ void merge33(float a0, float a1, float a2,
                                        float b0, float b1, float b2,
                                        float& z0, float& z1, float& z2,
                                        float& z3, float& z4, float& z5) {
    float e0, e1, e2, e3;
    merge22(a0, a2, b0, b2, e0, e1, e2, e3);   // evens
    float o0 = a1, o1 = b1;
    ce(o0, o1);                                 // odds
    z0 = e0;
    z1 = o0; z2 = e1; ce(z1, z2);
    z3 = o1; z4 = e2; ce(z3, z4);
    z5 = e3;
}

// Batcher odd-even merge of two sorted 5-chains; only the MIDDLE FOUR
// (ranks 4..7 of 10, i.e. y3..y6) are produced. Rest is dead code.
__device__ __forceinline__ void merge55_mid4(const float A[5], const float B[5],
                                             float& s0, float& s1, float& s2, float& s3) {
    // evens: A0,A2,A4 with B0,B2,B4 -> z0..z5
    float z0, z1, z2, z3, z4, z5;
    merge33(A[0], A[2], A[4], B[0], B[2], B[4], z0, z1, z2, z3, z4, z5);
    // odds: A1,A3 with B1,B3 -> w0..w3
    float w0, w1, w2, w3;
    merge22(A[1], A[3], B[1], B[3], w0, w1, w2, w3);
    // y3,y4 = CE(w1,z2); y5,y6 = CE(w2,z3)
    s0 = fminf(w1, z2); s1 = fmaxf(w1, z2);
    s2 = fminf(w2, z3); s3 = fmaxf(w2, z3);
}

// Median of 25 given 5 ascending-sorted columns c[j][0..4] (j = 0..4).
__device__ __forceinline__ float med25_from_sorted_cols(
    const float c0[5], const float c1[5], const float c2[5],
    const float c3[5], const float c4[5]) {
    // Rows of the column-sorted matrix; sort each (DCE keeps only the
    // 13 candidate-band outputs).
    float r0[5] = {c0[0], c1[0], c2[0], c3[0], c4[0]};
    float r1[5] = {c0[1], c1[1], c2[1], c3[1], c4[1]};
    float r2[5] = {c0[2], c1[2], c2[2], c3[2], c4[2]};
    float r3[5] = {c0[3], c1[3], c2[3], c3[3], c4[3]};
    float r4[5] = {c0[4], c1[4], c2[4], c3[4], c4[4]};
    sort5(r0[0], r0[1], r0[2], r0[3], r0[4]);
    sort5(r1[0], r1[1], r1[2], r1[3], r1[4]);
    sort5(r2[0], r2[1], r2[2], r2[3], r2[4]);
    sort5(r3[0], r3[1], r3[2], r3[3], r3[4]);
    sort5(r4[0], r4[1], r4[2], r4[3], r4[4]);

    // Candidate band (13 elems): r0[3..4], r1[2..4], r2[1..3], r3[0..2], r4[0..1]
    float A[5], B[5];
    merge23(r0[3], r0[4], r1[2], r1[3], r1[4], A[0], A[1], A[2], A[3], A[4]);
    merge23(r4[0], r4[1], r3[0], r3[1], r3[2], B[0], B[1], B[2], B[3], B[4]);

    float s0, s1, s2, s3;                 // S[3..6] of merge(A,B)
    merge55_mid4(A, B, s0, s1, s2, s3);

    // med13 == med7({S[3..6], r2[1..3]}); drop global min & max -> med5.
    float t0 = r2[1], t1 = r2[2], t2 = r2[3];
    float u0 = fmaxf(s0, t0);   // global min removed
    float u3 = fminf(s3, t2);   // global max removed
    float m0 = u0, m1 = s1, m2 = s2, m3 = u3, m4 = t1;
    sort5(m0, m1, m2, m3, m4);  // only m2 consumed -> DCE trims
    return m2;
}

__global__ __launch_bounds__(256)
void median5x5_kernel(const float* __restrict__ in, float* __restrict__ out) {
    __shared__ float tile[SMEM_H][SMEM_W];

    const int n   = blockIdx.z;
    const int x0b = blockIdx.x * TILE_W;
    const int y0b = blockIdx.y * TILE_H;
    const float* img = in + (size_t)n * IMG_H * IMG_W;

    const int tid = threadIdx.y * 32 + threadIdx.x;

    // Cooperative, coalesced-ish tile load with zero padding.
    #pragma unroll
    for (int i = tid; i < SMEM_H * SMEM_W; i += 256) {
        int r = i / SMEM_W;
        int c = i - r * SMEM_W;
        int gy = y0b + r - 2;
        int gx = x0b + c - 2;
        float v = 0.0f;
        if ((unsigned)gy < IMG_H && (unsigned)gx < IMG_W) v = img[gy * IMG_W + gx];
        tile[r][c] = v;
    }
    __syncthreads();

    const int tx = threadIdx.x;
    const int ty = threadIdx.y;

    // Load 8 columns x 5 window rows via two aligned float4 LDS per row.
    float col[8][5];
    #pragma unroll
    for (int i = 0; i < 5; i++) {
        const float4 va = *reinterpret_cast<const float4*>(&tile[ty + i][tx * 4]);
        const float4 vb = *reinterpret_cast<const float4*>(&tile[ty + i][tx * 4 + 4]);
        col[0][i] = va.x; col[1][i] = va.y; col[2][i] = va.z; col[3][i] = va.w;
        col[4][i] = vb.x; col[5][i] = vb.y; col[6][i] = vb.z; col[7][i] = vb.w;
    }
    #pragma unroll
    for (int j = 0; j < 8; j++)
        sort5(col[j][0], col[j][1], col[j][2], col[j][3], col[j][4]);

    float4 res;
    res.x = med25_from_sorted_cols(col[0], col[1], col[2], col[3], col[4]);
    res.y = med25_from_sorted_cols(col[1], col[2], col[3], col[4], col[5]);
    res.z = med25_from_sorted_cols(col[2], col[3], col[4], col[5], col[6]);
    res.w = med25_from_sorted_cols(col[3], col[4], col[5], col[6], col[7]);

    const int y = y0b + ty;
    const int x = x0b + tx * 4;
    *reinterpret_cast<float4*>(out + (size_t)n * IMG_H * IMG_W + (size_t)y * IMG_W + x) = res;
}

extern "C" void kernel_launch(void* const* d_in, const int* in_sizes, int n_in,
                              void* d_out, int out_size) {
    (void)in_sizes; (void)n_in; (void)out_size;
    const float* in = (const float*)d_in[0];
    float* out = (float*)d_out;

    dim3 block(32, 8, 1);
    dim3 grid(IMG_W / TILE_W, IMG_H / TILE_H, NIMG);
    median5x5_kernel<<<grid, block>>>(in, out);
}

// round 2
// speedup vs baseline: 1.2400x; 1.2400x over previous
#include <cuda_runtime.h>
#include <cuda_fp16.h>

// MedianBlur 5x5, fp32 I/O, 12 images of 1024x1024, zero padding (same).
// Round-2: packed half2 network — each thread computes 8 horizontal outputs
// as 4 half2 pixel-pairs (pixels q and q+4 share one register lane pair).
// Median is an exact order statistic, so the only error is fp16 rounding of
// the inputs (<= 2^-11 relative), far under the 1e-3 threshold (norm-based).

#define IMG_H 1024
#define IMG_W 1024
#define NIMG  12

#define TILE_W 256            // output cols per block (32 threads * 8 px)
#define TILE_H 8              // output rows per block
#define SMEM_USED_W 260       // TILE_W + 4 halo
#define SMEM_W 264            // padded: row stride 528B, 16B-aligned
#define SMEM_H 12             // TILE_H + 4 halo

typedef __half2 h2;

__device__ __forceinline__ h2 mn2(h2 a, h2 b) { return __hmin2(a, b); }
__device__ __forceinline__ h2 mx2(h2 a, h2 b) { return __hmax2(a, b); }

__device__ __forceinline__ void ce(h2& a, h2& b) {
    h2 t = mn2(a, b);
    b = mx2(a, b);
    a = t;
}

// 9-CE optimal sorting network for 5 elements (ascending), element-wise on half2.
__device__ __forceinline__ void sort5(h2& v0, h2& v1, h2& v2, h2& v3, h2& v4) {
    ce(v0, v1); ce(v3, v4); ce(v2, v4); ce(v2, v3); ce(v0, v3);
    ce(v0, v2); ce(v1, v4); ce(v1, v3); ce(v1, v2);
}

// Merge sorted pair (a0<=a1) with sorted triple (b0<=b1<=b2) -> m0..m4.
__device__ __forceinline__ void merge23(h2 a0, h2 a1,
                                        h2 b0, h2 b1, h2 b2,
                                        h2& m0, h2& m1, h2& m2,
                                        h2& m3, h2& m4) {
    h2 x0 = mn2(a0, b0); h2 y0 = mx2(a0, b0);
    h2 x1 = mn2(y0, b1); h2 y1 = mx2(y0, b1);
    h2 x2 = mn2(y1, b2); h2 x3 = mx2(y1, b2);
    h2 w1 = mn2(a1, x1); h2 z1 = mx2(a1, x1);
    h2 w2 = mn2(z1, x2); h2 z2 = mx2(z1, x2);
    h2 w3 = mn2(z2, x3); h2 w4 = mx2(z2, x3);
    m0 = x0; m1 = w1; m2 = w2; m3 = w3; m4 = w4;
}

// Merge two sorted pairs -> m0..m3 (3 CE).
__device__ __forceinline__ void merge22(h2 a0, h2 a1, h2 b0, h2 b1,
                                        h2& m0, h2& m1, h2& m2, h2& m3) {
    m0 = mn2(a0, b0); h2 t = mx2(a0, b0);
    m3 = mx2(a1, b1); h2 u = mn2(a1, b1);
    m1 = mn2(t, u);   m2 = mx2(t, u);
}

// Batcher odd-even merge of two sorted triples -> z0..z5 (6 CE).
__device__ __forceinline__ void merge33(h2 a0, h2 a1, h2 a2,
                                        h2 b0, h2 b1, h2 b2,
                                        h2& z0, h2& z1, h2& z2,
                                        h2& z3, h2& z4, h2& z5) {
    h2 e0, e1, e2, e3;
    merge22(a0, a2, b0, b2, e0, e1, e2, e3);
    h2 o0 = a1, o1 = b1;
    ce(o0, o1);
    z0 = e0;
    z1 = o0; z2 = e1; ce(z1, z2);
    z3 = o1; z4 = e2; ce(z3, z4);
    z5 = e3;
}

// Batcher odd-even merge of two sorted 5-chains; only ranks 3..6 of 10 produced.
__device__ __forceinline__ void merge55_mid4(const h2 A[5], const h2 B[5],
                                             h2& s0, h2& s1, h2& s2, h2& s3) {
    h2 z0, z1, z2, z3, z4, z5;
    merge33(A[0], A[2], A[4], B[0], B[2], B[4], z0, z1, z2, z3, z4, z5);
    h2 w0, w1, w2, w3;
    merge22(A[1], A[3], B[1], B[3], w0, w1, w2, w3);
    s0 = mn2(w1, z2); s1 = mx2(w1, z2);
    s2 = mn2(w2, z3); s3 = mx2(w2, z3);
}

// Median of 25 given 5 ascending-sorted columns (element-wise on half2 lanes).
__device__ __forceinline__ h2 med25_from_sorted_cols(
    const h2 c0[5], const h2 c1[5], const h2 c2[5],
    const h2 c3[5], const h2 c4[5]) {
    h2 r0[5] = {c0[0], c1[0], c2[0], c3[0], c4[0]};
    h2 r1[5] = {c0[1], c1[1], c2[1], c3[1], c4[1]};
    h2 r2[5] = {c0[2], c1[2], c2[2], c3[2], c4[2]};
    h2 r3[5] = {c0[3], c1[3], c2[3], c3[3], c4[3]};
    h2 r4[5] = {c0[4], c1[4], c2[4], c3[4], c4[4]};
    sort5(r0[0], r0[1], r0[2], r0[3], r0[4]);
    sort5(r1[0], r1[1], r1[2], r1[3], r1[4]);
    sort5(r2[0], r2[1], r2[2], r2[3], r2[4]);
    sort5(r3[0], r3[1], r3[2], r3[3], r3[4]);
    sort5(r4[0], r4[1], r4[2], r4[3], r4[4]);

    // Candidate band (13 elems): r0[3..4], r1[2..4], r2[1..3], r3[0..2], r4[0..1]
    h2 A[5], B[5];
    merge23(r0[3], r0[4], r1[2], r1[3], r1[4], A[0], A[1], A[2], A[3], A[4]);
    merge23(r4[0], r4[1], r3[0], r3[1], r3[2], B[0], B[1], B[2], B[3], B[4]);

    h2 s0, s1, s2, s3;
    merge55_mid4(A, B, s0, s1, s2, s3);

    // med13 == med7({S[3..6], r2[1..3]}); drop global min & max -> med5.
    h2 u0 = mx2(s0, r2[1]);
    h2 u3 = mn2(s3, r2[3]);
    h2 m0 = u0, m1 = s1, m2 = s2, m3 = u3, m4 = r2[2];
    sort5(m0, m1, m2, m3, m4);   // only m2 consumed -> DCE trims
    return m2;
}

__global__ __launch_bounds__(256)
void median5x5_h2_kernel(const float* __restrict__ in, float* __restrict__ out) {
    __shared__ __half tile[SMEM_H][SMEM_W];

    const int n   = blockIdx.z;
    const int x0b = blockIdx.x * TILE_W;
    const int y0b = blockIdx.y * TILE_H;
    const float* img = in + (size_t)n * IMG_H * IMG_W;

    const int tx = threadIdx.x;
    const int ty = threadIdx.y;

    // Cooperative tile load (fp32 -> fp16), zero padding.
    for (int r = ty; r < SMEM_H; r += TILE_H) {
        const int gy = y0b + r - 2;
        #pragma unroll
        for (int c = tx; c < SMEM_USED_W; c += 32) {
            const int gx = x0b + c - 2;
            float v = 0.0f;
            if ((unsigned)gy < IMG_H && (unsigned)gx < IMG_W) v = img[gy * IMG_W + gx];
            tile[r][c] = __float2half_rn(v);
        }
    }
    __syncthreads();

    // Each thread: 12 consecutive halfs per window row (cols tx*8 .. tx*8+11),
    // packed into 8 half2 column-pairs P_k = (h[k], h[k+4]) serving pixel
    // pairs (q, q+4) for q = 0..3.
    h2 col[8][5];
    #pragma unroll
    for (int i = 0; i < 5; i++) {
        const __half* rp = &tile[ty + i][tx * 8];
        const uint4 A = *reinterpret_cast<const uint4*>(rp);       // halfs 0..7
        const uint2 Bv = *reinterpret_cast<const uint2*>(rp + 8);  // halfs 8..11
        const unsigned u[6] = {A.x, A.y, A.z, A.w, Bv.x, Bv.y};
        #pragma unroll
        for (int k = 0; k < 8; k++) {
            // even k: (u[i].lo, u[i+2].lo) -> 0x5410 ; odd k: hi halves -> 0x7632
            const unsigned sel = (k & 1) ? 0x7632u : 0x5410u;
            unsigned p = __byte_perm(u[k >> 1], u[(k >> 1) + 2], sel);
            col[k][i] = *reinterpret_cast<h2*>(&p);
        }
    }

    #pragma unroll
    for (int k = 0; k < 8; k++)
        sort5(col[k][0], col[k][1], col[k][2], col[k][3], col[k][4]);

    h2 r0 = med25_from_sorted_cols(col[0], col[1], col[2], col[3], col[4]);
    h2 r1 = med25_from_sorted_cols(col[1], col[2], col[3], col[4], col[5]);
    h2 r2 = med25_from_sorted_cols(col[2], col[3], col[4], col[5], col[6]);
    h2 r3 = med25_from_sorted_cols(col[3], col[4], col[5], col[6], col[7]);

    // lo lanes -> pixels x0+0..3, hi lanes -> pixels x0+4..7
    float4 oA, oB;
    oA.x = __low2float(r0);  oA.y = __low2float(r1);
    oA.z = __low2float(r2);  oA.w = __low2float(r3);
    oB.x = __high2float(r0); oB.y = __high2float(r1);
    oB.z = __high2float(r2); oB.w = __high2float(r3);

    float* orow = out + (size_t)n * IMG_H * IMG_W
                      + (size_t)(y0b + ty) * IMG_W + x0b + tx * 8;
    *reinterpret_cast<float4*>(orow)     = oA;
    *reinterpret_cast<float4*>(orow + 4) = oB;
}

extern "C" void kernel_launch(void* const* d_in, const int* in_sizes, int n_in,
                              void* d_out, int out_size) {
    (void)in_sizes; (void)n_in; (void)out_size;
    const float* in = (const float*)d_in[0];
    float* out = (float*)d_out;

    dim3 block(32, TILE_H, 1);
    dim3 grid(IMG_W / TILE_W, IMG_H / TILE_H, NIMG);
    median5x5_h2_kernel<<<grid, block>>>(in, out);
}

// round 3
// speedup vs baseline: 1.9489x; 1.5717x over previous
#include <cuda_runtime.h>
#include <cuda_fp16.h>

// MedianBlur 5x5, fp32 I/O, 12 images of 1024x1024, zero padding (same).
// Round-3: occupancy push. 4 outputs/thread as 2 half2 pixel-pairs at
// distance 2; 6 packed sorted columns; candidate-band med25.
// __launch_bounds__(256,6) -> 42-reg cap -> 6 CTAs/SM (48 warps, 75% occ).

#define IMG_H 1024
#define IMG_W 1024
#define NIMG  12

#define TILE_W 128            // output cols per block (32 threads * 4 px)
#define TILE_H 8              // output rows per block
#define SMEM_W 136            // loaded cols: gx in [x0b-4, x0b+132)
#define SMEM_H 12             // TILE_H + 4 halo

typedef __half2 h2;

__device__ __forceinline__ h2 mn2(h2 a, h2 b) { return __hmin2(a, b); }
__device__ __forceinline__ h2 mx2(h2 a, h2 b) { return __hmax2(a, b); }

__device__ __forceinline__ void ce(h2& a, h2& b) {
    h2 t = mn2(a, b);
    b = mx2(a, b);
    a = t;
}

// 9-CE optimal sorting network for 5 elements (ascending), element-wise on half2.
__device__ __forceinline__ void sort5(h2& v0, h2& v1, h2& v2, h2& v3, h2& v4) {
    ce(v0, v1); ce(v3, v4); ce(v2, v4); ce(v2, v3); ce(v0, v3);
    ce(v0, v2); ce(v1, v4); ce(v1, v3); ce(v1, v2);
}

// Merge sorted pair (a0<=a1) with sorted triple (b0<=b1<=b2) -> m0..m4.
__device__ __forceinline__ void merge23(h2 a0, h2 a1,
                                        h2 b0, h2 b1, h2 b2,
                                        h2& m0, h2& m1, h2& m2,
                                        h2& m3, h2& m4) {
    h2 x0 = mn2(a0, b0); h2 y0 = mx2(a0, b0);
    h2 x1 = mn2(y0, b1); h2 y1 = mx2(y0, b1);
    h2 x2 = mn2(y1, b2); h2 x3 = mx2(y1, b2);
    h2 w1 = mn2(a1, x1); h2 z1 = mx2(a1, x1);
    h2 w2 = mn2(z1, x2); h2 z2 = mx2(z1, x2);
    h2 w3 = mn2(z2, x3); h2 w4 = mx2(z2, x3);
    m0 = x0; m1 = w1; m2 = w2; m3 = w3; m4 = w4;
}

// Merge two sorted pairs -> m0..m3 (3 CE).
__device__ __forceinline__ void merge22(h2 a0, h2 a1, h2 b0, h2 b1,
                                        h2& m0, h2& m1, h2& m2, h2& m3) {
    m0 = mn2(a0, b0); h2 t = mx2(a0, b0);
    m3 = mx2(a1, b1); h2 u = mn2(a1, b1);
    m1 = mn2(t, u);   m2 = mx2(t, u);
}

// Batcher odd-even merge of two sorted triples -> z0..z5 (6 CE).
__device__ __forceinline__ void merge33(h2 a0, h2 a1, h2 a2,
                                        h2 b0, h2 b1, h2 b2,
                                        h2& z0, h2& z1, h2& z2,
                                        h2& z3, h2& z4, h2& z5) {
    h2 e0, e1, e2, e3;
    merge22(a0, a2, b0, b2, e0, e1, e2, e3);
    h2 o0 = a1, o1 = b1;
    ce(o0, o1);
    z0 = e0;
    z1 = o0; z2 = e1; ce(z1, z2);
    z3 = o1; z4 = e2; ce(z3, z4);
    z5 = e3;
}

// Batcher odd-even merge of two sorted 5-chains; only ranks 3..6 of 10 produced.
__device__ __forceinline__ void merge55_mid4(const h2 A[5], const h2 B[5],
                                             h2& s0, h2& s1, h2& s2, h2& s3) {
    h2 z0, z1, z2, z3, z4, z5;
    merge33(A[0], A[2], A[4], B[0], B[2], B[4], z0, z1, z2, z3, z4, z5);
    h2 w0, w1, w2, w3;
    merge22(A[1], A[3], B[1], B[3], w0, w1, w2, w3);
    s0 = mn2(w1, z2); s1 = mx2(w1, z2);
    s2 = mn2(w2, z3); s3 = mx2(w2, z3);
}

// Median of 25 given 5 ascending-sorted columns (element-wise on half2 lanes).
__device__ __forceinline__ h2 med25_from_sorted_cols(
    const h2 c0[5], const h2 c1[5], const h2 c2[5],
    const h2 c3[5], const h2 c4[5]) {
    h2 r0[5] = {c0[0], c1[0], c2[0], c3[0], c4[0]};
    h2 r1[5] = {c0[1], c1[1], c2[1], c3[1], c4[1]};
    h2 r2[5] = {c0[2], c1[2], c2[2], c3[2], c4[2]};
    h2 r3[5] = {c0[3], c1[3], c2[3], c3[3], c4[3]};
    h2 r4[5] = {c0[4], c1[4], c2[4], c3[4], c4[4]};
    sort5(r0[0], r0[1], r0[2], r0[3], r0[4]);
    sort5(r1[0], r1[1], r1[2], r1[3], r1[4]);
    sort5(r2[0], r2[1], r2[2], r2[3], r2[4]);
    sort5(r3[0], r3[1], r3[2], r3[3], r3[4]);
    sort5(r4[0], r4[1], r4[2], r4[3], r4[4]);

    // Candidate band (13 elems): r0[3..4], r1[2..4], r2[1..3], r3[0..2], r4[0..1]
    h2 A[5], B[5];
    merge23(r0[3], r0[4], r1[2], r1[3], r1[4], A[0], A[1], A[2], A[3], A[4]);
    merge23(r4[0], r4[1], r3[0], r3[1], r3[2], B[0], B[1], B[2], B[3], B[4]);

    h2 s0, s1, s2, s3;
    merge55_mid4(A, B, s0, s1, s2, s3);

    // med13 == med7({S[3..6], r2[1..3]}); drop global min & max -> med5.
    h2 u0 = mx2(s0, r2[1]);
    h2 u3 = mn2(s3, r2[3]);
    h2 m0 = u0, m1 = s1, m2 = s2, m3 = u3, m4 = r2[2];
    sort5(m0, m1, m2, m3, m4);   // only m2 consumed -> DCE trims
    return m2;
}

__global__ __launch_bounds__(256, 6)
void median5x5_h2_kernel(const float* __restrict__ in, float* __restrict__ out) {
    __shared__ __half tile[SMEM_H][SMEM_W];

    const int n   = blockIdx.z;
    const int x0b = blockIdx.x * TILE_W;
    const int y0b = blockIdx.y * TILE_H;
    const float* img = in + (size_t)n * IMG_H * IMG_W;

    const int tx = threadIdx.x;
    const int ty = threadIdx.y;
    const int tid = ty * 32 + tx;

    // Vectorized cooperative tile load (fp32 -> fp16), zero padding.
    // smem col c holds gx = x0b - 4 + c, c in [0, 136).
    #pragma unroll
    for (int i = tid; i < SMEM_H * (SMEM_W / 4); i += 256) {
        const int r  = i / (SMEM_W / 4);
        const int c4 = i - r * (SMEM_W / 4);
        const int gy  = y0b + r - 2;
        const int gx0 = x0b - 4 + c4 * 4;
        float4 f = make_float4(0.f, 0.f, 0.f, 0.f);
        if ((unsigned)gy < IMG_H) {
            const float* rowp = img + (size_t)gy * IMG_W;
            if (gx0 >= 0 && gx0 + 3 < IMG_W) {
                f = *reinterpret_cast<const float4*>(rowp + gx0);
            } else {
                if ((unsigned)gx0       < IMG_W) f.x = rowp[gx0];
                if ((unsigned)(gx0 + 1) < IMG_W) f.y = rowp[gx0 + 1];
                if ((unsigned)(gx0 + 2) < IMG_W) f.z = rowp[gx0 + 2];
                if ((unsigned)(gx0 + 3) < IMG_W) f.w = rowp[gx0 + 3];
            }
        }
        const h2 h01 = __float22half2_rn(make_float2(f.x, f.y));
        const h2 h23 = __float22half2_rn(make_float2(f.z, f.w));
        uint2 st;
        st.x = *reinterpret_cast<const unsigned*>(&h01);
        st.y = *reinterpret_cast<const unsigned*>(&h23);
        *reinterpret_cast<uint2*>(&tile[r][c4 * 4]) = st;
    }
    __syncthreads();

    // Thread handles pixels p0..p0+3 (p0 = tx*4) as pairs (p0,p0+2),(p0+1,p0+3).
    // Pixel p needs smem cols p+2..p+6. Packed col P_m = (h[p0+2+m], h[p0+4+m]),
    // m = 0..5; network A uses P0..P4, network B uses P1..P5.
    const int p0 = tx * 4;
    h2 col[6][5];
    #pragma unroll
    for (int i = 0; i < 5; i++) {
        const __half* rp = &tile[ty + i][p0];
        const uint2 a = *reinterpret_cast<const uint2*>(rp);       // halfs 0..3
        const uint2 b = *reinterpret_cast<const uint2*>(rp + 4);   // halfs 4..7
        const unsigned cw = *reinterpret_cast<const unsigned*>(rp + 8); // halfs 8..9
        const unsigned u[5] = {a.x, a.y, b.x, b.y, cw};
        #pragma unroll
        for (int m = 0; m < 6; m++) {
            const int w1 = (m + 2) >> 1;
            const int w2 = (m + 4) >> 1;
            const unsigned sel = (m & 1) ? 0x7632u : 0x5410u;
            unsigned p = __byte_perm(u[w1], u[w2], sel);
            col[m][i] = *reinterpret_cast<h2*>(&p);
        }
    }

    #pragma unroll
    for (int m = 0; m < 6; m++)
        sort5(col[m][0], col[m][1], col[m][2], col[m][3], col[m][4]);

    const h2 rA = med25_from_sorted_cols(col[0], col[1], col[2], col[3], col[4]);
    const h2 rB = med25_from_sorted_cols(col[1], col[2], col[3], col[4], col[5]);

    float4 res;
    res.x = __low2float(rA);    // pixel p0
    res.y = __low2float(rB);    // pixel p0+1
    res.z = __high2float(rA);   // pixel p0+2
    res.w = __high2float(rB);   // pixel p0+3

    float* orow = out + (size_t)n * IMG_H * IMG_W
                      + (size_t)(y0b + ty) * IMG_W + x0b + p0;
    *reinterpret_cast<float4*>(orow) = res;
}

extern "C" void kernel_launch(void* const* d_in, const int* in_sizes, int n_in,
                              void* d_out, int out_size) {
    (void)in_sizes; (void)n_in; (void)out_size;
    const float* in = (const float*)d_in[0];
    float* out = (float*)d_out;

    dim3 block(32, TILE_H, 1);
    dim3 grid(IMG_W / TILE_W, IMG_H / TILE_H, NIMG);
    median5x5_h2_kernel<<<grid, block>>>(in, out);
}